// round 13
// baseline (speedup 1.0000x reference)
#include <cuda_runtime.h>
#include <cuda_bf16.h>
#include <cstdint>

#define BATCH      524288
#define N_QUBITS   16
#define NUM_CLS    10
#define TPB        512
#define RPC        4096                       // rows per CTA
#define GRID       (BATCH / RPC)              // 128 CTAs, single wave
#define RPT        (RPC / TPB)                // 8 rows per thread
#define SMEM_BYTES (RPC * NUM_CLS * 4)        // 160 KB output tile

// Phase-separated memory streams: each CTA computes its whole 160KB output
// tile into smem (DRAM sees only the read stream), then emits it as one TMA
// bulk store (DRAM sees only the write stream). Avoids fine-grained R/W
// interleave on the HBM bus, the hypothesized cause of the 40% ceiling.
__global__ __launch_bounds__(TPB) void qllp_kernel(
    const float* __restrict__ x,       // [BATCH, 16]
    const float* __restrict__ params,  // [16]
    float*       __restrict__ out)     // [BATCH, 10]
{
    extern __shared__ __align__(128) float s_out[];   // RPC*10 floats

    const int tid = threadIdx.x;
    const size_t base = (size_t)blockIdx.x * RPC;

    const float pr12 = __ldg(&params[12]);
    const float pr13 = __ldg(&params[13]);
    const float pr14 = __ldg(&params[14]);
    const float pr15 = __ldg(&params[15]);
    const float PI = 3.14159265358979323846f;

    // Front-batched reads: 8 independent LDG.128 per thread (MLP=8).
    float4 v[RPT];
    #pragma unroll
    for (int j = 0; j < RPT; j++) {
        const size_t row = base + tid + (size_t)j * TPB;
        v[j] = *reinterpret_cast<const float4*>(x + row * N_QUBITS + 12);
    }

    #pragma unroll
    for (int j = 0; j < RPT; j++) {
        const float c0 = __cosf(PI * v[j].x + pr12);   // qubit 12
        const float c1 = __cosf(PI * v[j].y + pr13);   // qubit 13
        const float c2 = __cosf(PI * v[j].z + pr14);   // qubit 14
        const float c3 = __cosf(PI * v[j].w + pr15);   // qubit 15

        const float a0 = 0.5f + 0.5f * c0, b0 = 0.5f - 0.5f * c0;
        const float a1 = 0.5f + 0.5f * c1, b1 = 0.5f - 0.5f * c1;
        const float a2 = 0.5f + 0.5f * c2, b2 = 0.5f - 0.5f * c2;
        const float a3 = 0.5f + 0.5f * c3, b3 = 0.5f - 0.5f * c3;

        // bits[s,i] = (s >> (15-i)) & 1 -> qubit12 = bit3 ... qubit15 = bit0
        const float m00 = a1 * a2, m01 = a1 * b2, m10 = b1 * a2, m11 = b1 * b2;
        const float g0 = m00 * a3, g1 = m00 * b3, g2 = m01 * a3, g3 = m01 * b3;
        const float g4 = m10 * a3, g5 = m10 * b3, g6 = m11 * a3, g7 = m11 * b3;

        float t[NUM_CLS];
        t[0] = a0 * g0;  t[1] = a0 * g1;  t[2] = a0 * g2;  t[3] = a0 * g3;
        t[4] = a0 * g4;  t[5] = a0 * g5;  t[6] = a0 * g6;  t[7] = a0 * g7;
        t[8] = b0 * g0;  t[9] = b0 * g1;

        float sum = t[0];
        #pragma unroll
        for (int s = 1; s < NUM_CLS; s++) sum += t[s];
        const float inv = __fdividef(1.0f, sum);

        float2* dst2 = reinterpret_cast<float2*>(
            s_out + (tid + (size_t)j * TPB) * NUM_CLS);
        #pragma unroll
        for (int s = 0; s < NUM_CLS / 2; s++)
            dst2[s] = make_float2(t[2 * s] * inv, t[2 * s + 1] * inv);
    }

    __syncthreads();

    // Write phase: one 160 KB TMA bulk store of the whole CTA tile.
    if (tid == 0) {
        uint32_t saddr;
        asm("{ .reg .u64 t; cvta.to.shared.u64 t, %1; cvt.u32.u64 %0, t; }"
            : "=r"(saddr) : "l"(s_out));
        float* gdst = out + base * NUM_CLS;
        asm volatile("fence.proxy.async.shared::cta;" ::: "memory");
        asm volatile("cp.async.bulk.global.shared::cta.bulk_group [%0], [%1], %2;"
                     :: "l"(gdst), "r"(saddr), "r"((uint32_t)SMEM_BYTES)
                     : "memory");
        asm volatile("cp.async.bulk.commit_group;" ::: "memory");
        asm volatile("cp.async.bulk.wait_group 0;" ::: "memory");
    }
}

extern "C" void kernel_launch(void* const* d_in, const int* in_sizes, int n_in,
                              void* d_out, int out_size) {
    const float* x      = (const float*)d_in[0];
    const float* params = (const float*)d_in[1];
    float*       out    = (float*)d_out;
    cudaFuncSetAttribute(qllp_kernel,
                         cudaFuncAttributeMaxDynamicSharedMemorySize, SMEM_BYTES);
    qllp_kernel<<<GRID, TPB, SMEM_BYTES>>>(x, params, out);
}